// round 6
// baseline (speedup 1.0000x reference)
#include <cuda_runtime.h>
#include <cuda_fp16.h>
#include <cstdint>

#define BATCH 2
#define CH    64
#define NTOK  4608
#define BM    64
#define BN    64
#define NT    72               // total KV tiles
#define NTH   36               // tiles per KV half
#define SCALE 0.125f
#define LOG2E 1.4426950408889634f
#define PH    72               // padded tile row length in halves (144 B)

// Scratch (fp16): Q,K token-major [B][N][C]; V channel-major [B][C][N]
__device__ __half g_Q[BATCH * NTOK * CH];
__device__ __half g_K[BATCH * NTOK * CH];
__device__ __half g_V[BATCH * CH * NTOK];

// ---------------------------------------------------------------------------
__device__ __forceinline__ void mma_f16(float* c, const uint32_t* a,
                                        uint32_t b0, uint32_t b1) {
    asm volatile(
        "mma.sync.aligned.m16n8k16.row.col.f32.f16.f16.f32 "
        "{%0,%1,%2,%3}, {%4,%5,%6,%7}, {%8,%9}, {%0,%1,%2,%3};"
        : "+f"(c[0]), "+f"(c[1]), "+f"(c[2]), "+f"(c[3])
        : "r"(a[0]), "r"(a[1]), "r"(a[2]), "r"(a[3]), "r"(b0), "r"(b1));
}
__device__ __forceinline__ void cp16(uint32_t dst, const void* src) {
    asm volatile("cp.async.ca.shared.global [%0], [%1], 16;"
                 :: "r"(dst), "l"(src));
}

// ---------------------------------------------------------------------------
// Projection -> fp16, 2 tokens per thread (amortize weight LDS).
// z=0: Q from x (pre-scaled SCALE*LOG2E, [n][c]), z=1: K ([n][c]),
// z=2: V from h TRANSPOSED ([c][n]).
// ---------------------------------------------------------------------------
__global__ __launch_bounds__(128) void proj_kernel(
    const float* __restrict__ x, const float* __restrict__ h,
    const float* __restrict__ Wq, const float* __restrict__ bq,
    const float* __restrict__ Wk, const float* __restrict__ bk,
    const float* __restrict__ Wv, const float* __restrict__ bv)
{
    __shared__ float Ws[CH * CH];
    __shared__ float bs[CH];

    const int z = blockIdx.z;
    const float* inp  = (z == 0) ? x  : h;
    const float* W    = (z == 0) ? Wq : (z == 1) ? Wk : Wv;
    const float* bias = (z == 0) ? bq : (z == 1) ? bk : bv;

    const int tid = threadIdx.x;
    #pragma unroll
    for (int i = tid; i < CH * CH; i += 128) Ws[i] = W[i];
    if (tid < CH) bs[tid] = bias[tid];
    __syncthreads();

    const int b  = blockIdx.y;
    const int n0 = blockIdx.x * 256 + tid;     // token A
    const int n1 = n0 + 128;                   // token B

    float acc0[CH], acc1[CH];
    #pragma unroll
    for (int o = 0; o < CH; o++) { acc0[o] = bs[o]; acc1[o] = bs[o]; }

    const float* ic = inp + (size_t)b * CH * NTOK;
    #pragma unroll
    for (int c4 = 0; c4 < CH / 4; c4++) {
        float a0[4], a1[4];
        #pragma unroll
        for (int j = 0; j < 4; j++) {
            a0[j] = ic[(size_t)(c4 * 4 + j) * NTOK + n0];
            a1[j] = ic[(size_t)(c4 * 4 + j) * NTOK + n1];
        }
        #pragma unroll
        for (int o = 0; o < CH; o++) {
            const float4 wv = *(const float4*)&Ws[o * CH + c4 * 4];
            acc0[o] += wv.x * a0[0] + wv.y * a0[1] + wv.z * a0[2] + wv.w * a0[3];
            acc1[o] += wv.x * a1[0] + wv.y * a1[1] + wv.z * a1[2] + wv.w * a1[3];
        }
    }

    if (z == 2) {
        __half* vd = g_V + (size_t)b * CH * NTOK;
        #pragma unroll
        for (int o = 0; o < CH; o++) {
            vd[(size_t)o * NTOK + n0] = __float2half_rn(acc0[o]);
            vd[(size_t)o * NTOK + n1] = __float2half_rn(acc1[o]);
        }
    } else {
        if (z == 0) {
            const float qs = SCALE * LOG2E;
            #pragma unroll
            for (int o = 0; o < CH; o++) { acc0[o] *= qs; acc1[o] *= qs; }
        }
        __half* base = (z == 0) ? g_Q : g_K;
        #pragma unroll
        for (int tk = 0; tk < 2; tk++) {
            const float* ac = tk ? acc1 : acc0;
            __half* dst = base + ((size_t)(b * NTOK + (tk ? n1 : n0))) * CH;
            #pragma unroll
            for (int o8 = 0; o8 < 8; o8++) {
                __half2 h0 = __floats2half2_rn(ac[o8 * 8 + 0], ac[o8 * 8 + 1]);
                __half2 h1 = __floats2half2_rn(ac[o8 * 8 + 2], ac[o8 * 8 + 3]);
                __half2 h2 = __floats2half2_rn(ac[o8 * 8 + 4], ac[o8 * 8 + 5]);
                __half2 h3 = __floats2half2_rn(ac[o8 * 8 + 6], ac[o8 * 8 + 7]);
                uint4 u;
                u.x = *(uint32_t*)&h0; u.y = *(uint32_t*)&h1;
                u.z = *(uint32_t*)&h2; u.w = *(uint32_t*)&h3;
                ((uint4*)dst)[o8] = u;
            }
        }
    }
}

// ---------------------------------------------------------------------------
// Split-KV FA2 fp16 attention. 256 threads = 8 warps.
// Warp w: rg = w&3 (rows rg*16..+15), ks = w>>2 (KV half: tiles ks*36+t).
// Softmax fully warp-local; P in registers; partner-warp merge at the end.
// smem: Qs[64][PH] @0; K stages [2 streams][3][64][PH] @9216;
//       V stages @64512; total 119808 B. Merge buffer reuses offset 0.
// ---------------------------------------------------------------------------
#define QS_B 0
#define KS_B 9216
#define VS_B (KS_B + 6 * 9216)
#define SMEM_BYTES (VS_B + 6 * 9216)   // 119808

__global__ __launch_bounds__(256, 1) void attn_kernel(float* __restrict__ out)
{
    extern __shared__ char smc[];
    const uint32_t sb = (uint32_t)__cvta_generic_to_shared(smc);

    const int b    = blockIdx.y;
    const int m0   = blockIdx.x * BM;
    const int tid  = threadIdx.x;
    const int lane = tid & 31;
    const int w    = tid >> 5;
    const int rg   = w & 3;
    const int ks   = w >> 2;
    const int gid  = lane >> 2;
    const int lc   = lane & 3;
    const int rlow  = rg * 16 + gid;
    const int rhigh = rlow + 8;

    // stage both streams' next tile: 8 cp16/thread
    auto stage_kv = [&](int slot, int tl) {
        #pragma unroll
        for (int s = 0; s < 2; s++) {
            const int tn = s * NTH + tl;
            #pragma unroll
            for (int i = 0; i < 2; i++) {
                const int j = tid + i * 256;     // 0..511
                const int r = j >> 3, c8 = j & 7;
                cp16(sb + KS_B + (s * 3 + slot) * 9216 + r * 144 + c8 * 16,
                     g_K + ((size_t)(b * NTOK + tn * BN) + r) * CH + c8 * 8);
                cp16(sb + VS_B + (s * 3 + slot) * 9216 + r * 144 + c8 * 16,
                     g_V + (size_t)b * CH * NTOK + (size_t)r * NTOK
                         + tn * BN + c8 * 8);
            }
        }
    };

    // ---- prologue ----
    {
        #pragma unroll
        for (int i = 0; i < 2; i++) {
            const int j = tid + i * 256;
            const int r = j >> 3, c8 = j & 7;
            cp16(sb + QS_B + r * 144 + c8 * 16,
                 g_Q + ((size_t)(b * NTOK + m0) + r) * CH + c8 * 8);
        }
        stage_kv(0, 0);
        asm volatile("cp.async.commit_group;");
        stage_kv(1, 1);
        asm volatile("cp.async.commit_group;");
        asm volatile("cp.async.wait_group 1;" ::: "memory");
        __syncthreads();
    }

    // ---- persistent Q A-fragments ----
    const __half* Qs = (const __half*)(smc + QS_B);
    uint32_t qa[4][4];
    #pragma unroll
    for (int kt = 0; kt < 4; kt++) {
        qa[kt][0] = *(const uint32_t*)&Qs[rlow  * PH + kt * 16 + 2 * lc];
        qa[kt][1] = *(const uint32_t*)&Qs[rhigh * PH + kt * 16 + 2 * lc];
        qa[kt][2] = *(const uint32_t*)&Qs[rlow  * PH + kt * 16 + 2 * lc + 8];
        qa[kt][3] = *(const uint32_t*)&Qs[rhigh * PH + kt * 16 + 2 * lc + 8];
    }

    float acc[8][4];
    #pragma unroll
    for (int nt = 0; nt < 8; nt++)
        #pragma unroll
        for (int i = 0; i < 4; i++) acc[nt][i] = 0.f;
    float mlo_run = -1e30f, mhi_run = -1e30f, llo = 0.f, lhi = 0.f;

    for (int t = 0; t < NTH; t++) {
        if (t > 0) {
            asm volatile("cp.async.wait_group 1;" ::: "memory");
            __syncthreads();
        }
        {   // prefetch tile t+2 (both streams)
            int tl = t + 2; if (tl >= NTH) tl -= NTH;
            stage_kv((t + 2) % 3, tl);
            asm volatile("cp.async.commit_group;");
        }

        const int slot = ks * 3 + (t % 3);

        // ---- scores S[16][64] (32 mma) ----
        const __half* Kc = (const __half*)(smc + KS_B + slot * 9216);
        float s[8][4];
        #pragma unroll
        for (int nt = 0; nt < 8; nt++)
            #pragma unroll
            for (int i = 0; i < 4; i++) s[nt][i] = 0.f;

        #pragma unroll
        for (int kt = 0; kt < 4; kt++) {
            #pragma unroll
            for (int nt = 0; nt < 8; nt++) {
                const int kj = nt * 8 + gid;
                uint32_t b0 = *(const uint32_t*)&Kc[kj * PH + kt * 16 + 2 * lc];
                uint32_t b1 = *(const uint32_t*)&Kc[kj * PH + kt * 16 + 2 * lc + 8];
                mma_f16(s[nt], qa[kt], b0, b1);
            }
        }

        // ---- warp-local softmax ----
        float tmlo = -1e30f, tmhi = -1e30f;
        #pragma unroll
        for (int nt = 0; nt < 8; nt++) {
            tmlo = fmaxf(tmlo, fmaxf(s[nt][0], s[nt][1]));
            tmhi = fmaxf(tmhi, fmaxf(s[nt][2], s[nt][3]));
        }
        tmlo = fmaxf(tmlo, __shfl_xor_sync(0xffffffffu, tmlo, 1));
        tmlo = fmaxf(tmlo, __shfl_xor_sync(0xffffffffu, tmlo, 2));
        tmhi = fmaxf(tmhi, __shfl_xor_sync(0xffffffffu, tmhi, 1));
        tmhi = fmaxf(tmhi, __shfl_xor_sync(0xffffffffu, tmhi, 2));
        const float mnlo = fmaxf(mlo_run, tmlo);
        const float mnhi = fmaxf(mhi_run, tmhi);
        const float alo  = exp2f(mlo_run - mnlo);
        const float ahi  = exp2f(mhi_run - mnhi);
        mlo_run = mnlo; mhi_run = mnhi;

        uint32_t pa[4][4];
        float slo = 0.f, shi = 0.f;
        #pragma unroll
        for (int nt = 0; nt < 8; nt++) {
            float p0 = exp2f(s[nt][0] - mnlo);
            float p1 = exp2f(s[nt][1] - mnlo);
            float p2 = exp2f(s[nt][2] - mnhi);
            float p3 = exp2f(s[nt][3] - mnhi);
            slo += p0 + p1;  shi += p2 + p3;
            __half2 lo2 = __floats2half2_rn(p0, p1);
            __half2 hi2 = __floats2half2_rn(p2, p3);
            pa[nt >> 1][(nt & 1) * 2]     = *(uint32_t*)&lo2;
            pa[nt >> 1][(nt & 1) * 2 + 1] = *(uint32_t*)&hi2;
        }
        slo += __shfl_xor_sync(0xffffffffu, slo, 1);
        slo += __shfl_xor_sync(0xffffffffu, slo, 2);
        shi += __shfl_xor_sync(0xffffffffu, shi, 1);
        shi += __shfl_xor_sync(0xffffffffu, shi, 2);
        llo = llo * alo + slo;
        lhi = lhi * ahi + shi;

        // ---- PV (32 mma) ----
        #pragma unroll
        for (int nt = 0; nt < 8; nt++) {
            acc[nt][0] *= alo; acc[nt][1] *= alo;
            acc[nt][2] *= ahi; acc[nt][3] *= ahi;
        }
        const __half* Vc = (const __half*)(smc + VS_B + slot * 9216);
        #pragma unroll
        for (int kt = 0; kt < 4; kt++) {
            #pragma unroll
            for (int nt = 0; nt < 8; nt++) {
                const int c = nt * 8 + gid;
                uint32_t b0 = *(const uint32_t*)&Vc[c * PH + kt * 16 + 2 * lc];
                uint32_t b1 = *(const uint32_t*)&Vc[c * PH + kt * 16 + 2 * lc + 8];
                mma_f16(acc[nt], pa[kt], b0, b1);
            }
        }
    }

    // ---- merge the two KV halves (partner warps, pointwise per lane) ----
    asm volatile("cp.async.wait_group 0;" ::: "memory");
    __syncthreads();
    float* mg = (float*)smc;                  // reuse Q/K smem
    const int mbase = (rg * 32 + lane) * 37;  // stride 37: conflict-free
    if (ks == 1) {
        #pragma unroll
        for (int nt = 0; nt < 8; nt++)
            #pragma unroll
            for (int i = 0; i < 4; i++) mg[mbase + nt * 4 + i] = acc[nt][i];
        mg[mbase + 32] = mlo_run;
        mg[mbase + 33] = mhi_run;
        mg[mbase + 34] = llo;
        mg[mbase + 35] = lhi;
    }
    __syncthreads();
    if (ks == 0) {
        const float m1lo = mg[mbase + 32], m1hi = mg[mbase + 33];
        const float l1lo = mg[mbase + 34], l1hi = mg[mbase + 35];
        const float Mlo = fmaxf(mlo_run, m1lo);
        const float Mhi = fmaxf(mhi_run, m1hi);
        const float c0lo = exp2f(mlo_run - Mlo), c1lo = exp2f(m1lo - Mlo);
        const float c0hi = exp2f(mhi_run - Mhi), c1hi = exp2f(m1hi - Mhi);
        const float Llo = llo * c0lo + l1lo * c1lo;
        const float Lhi = lhi * c0hi + l1hi * c1hi;
        const float ilo = c0lo / Llo, jlo = c1lo / Llo;
        const float ihi = c0hi / Lhi, jhi = c1hi / Lhi;

        float* ob = out + (size_t)b * CH * NTOK + m0;
        #pragma unroll
        for (int nt = 0; nt < 8; nt++) {
            const int c = nt * 8 + 2 * lc;
            const float o0 = acc[nt][0] * ilo + mg[mbase + nt * 4 + 0] * jlo;
            const float o1 = acc[nt][1] * ilo + mg[mbase + nt * 4 + 1] * jlo;
            const float o2 = acc[nt][2] * ihi + mg[mbase + nt * 4 + 2] * jhi;
            const float o3 = acc[nt][3] * ihi + mg[mbase + nt * 4 + 3] * jhi;
            ob[(size_t)c * NTOK + rlow]        = o0;
            ob[(size_t)(c + 1) * NTOK + rlow]  = o1;
            ob[(size_t)c * NTOK + rhigh]       = o2;
            ob[(size_t)(c + 1) * NTOK + rhigh] = o3;
        }
    }
}

// ---------------------------------------------------------------------------
extern "C" void kernel_launch(void* const* d_in, const int* in_sizes, int n_in,
                              void* d_out, int out_size)
{
    const float* x  = (const float*)d_in[0];
    const float* h  = (const float*)d_in[1];
    const float* Wq = (const float*)d_in[2];
    const float* bq = (const float*)d_in[3];
    const float* Wk = (const float*)d_in[4];
    const float* bk = (const float*)d_in[5];
    const float* Wv = (const float*)d_in[6];
    const float* bv = (const float*)d_in[7];
    float* out = (float*)d_out;

    cudaFuncSetAttribute(attn_kernel,
                         cudaFuncAttributeMaxDynamicSharedMemorySize, SMEM_BYTES);

    proj_kernel<<<dim3(NTOK / 256, BATCH, 3), 128>>>(x, h, Wq, bq, Wk, bk, Wv, bv);
    attn_kernel<<<dim3(NTOK / BM, BATCH), 256, SMEM_BYTES>>>(out);
}

// round 7
// speedup vs baseline: 1.1346x; 1.1346x over previous
#include <cuda_runtime.h>
#include <cuda_fp16.h>
#include <cstdint>

#define BATCH 2
#define CH    64
#define NTOK  4608
#define BM    64
#define BN    64
#define NT    72               // total KV tiles
#define NTH   36               // tiles per KV half
#define SCALE 0.125f
#define LOG2E 1.4426950408889634f
#define PH    72               // padded tile row length in halves (144 B)

// Scratch (fp16): Q,K token-major [B][N][C]; V channel-major [B][C][N]
__device__ __half g_Q[BATCH * NTOK * CH];
__device__ __half g_K[BATCH * NTOK * CH];
__device__ __half g_V[BATCH * CH * NTOK];

// ---------------------------------------------------------------------------
__device__ __forceinline__ void mma_f16(float* c, const uint32_t* a,
                                        uint32_t b0, uint32_t b1) {
    asm volatile(
        "mma.sync.aligned.m16n8k16.row.col.f32.f16.f16.f32 "
        "{%0,%1,%2,%3}, {%4,%5,%6,%7}, {%8,%9}, {%0,%1,%2,%3};"
        : "+f"(c[0]), "+f"(c[1]), "+f"(c[2]), "+f"(c[3])
        : "r"(a[0]), "r"(a[1]), "r"(a[2]), "r"(a[3]), "r"(b0), "r"(b1));
}
__device__ __forceinline__ void ldm4(uint32_t& r0, uint32_t& r1,
                                     uint32_t& r2, uint32_t& r3, uint32_t addr) {
    asm volatile("ldmatrix.sync.aligned.m8n8.x4.shared.b16 {%0,%1,%2,%3}, [%4];"
                 : "=r"(r0), "=r"(r1), "=r"(r2), "=r"(r3) : "r"(addr));
}
__device__ __forceinline__ void cp16(uint32_t dst, const void* src) {
    asm volatile("cp.async.ca.shared.global [%0], [%1], 16;"
                 :: "r"(dst), "l"(src));
}

// ---------------------------------------------------------------------------
// Projection -> fp16 (round-5 version). z=0: Q from x (pre-scaled SCALE*LOG2E,
// [n][c]), z=1: K from h ([n][c]), z=2: V from h TRANSPOSED ([c][n]).
// ---------------------------------------------------------------------------
__global__ __launch_bounds__(128) void proj_kernel(
    const float* __restrict__ x, const float* __restrict__ h,
    const float* __restrict__ Wq, const float* __restrict__ bq,
    const float* __restrict__ Wk, const float* __restrict__ bk,
    const float* __restrict__ Wv, const float* __restrict__ bv)
{
    __shared__ float Ws[CH * CH];
    __shared__ float bs[CH];

    const int z = blockIdx.z;
    const float* inp  = (z == 0) ? x  : h;
    const float* W    = (z == 0) ? Wq : (z == 1) ? Wk : Wv;
    const float* bias = (z == 0) ? bq : (z == 1) ? bk : bv;

    const int tid = threadIdx.x;
    #pragma unroll
    for (int i = tid; i < CH * CH; i += 128) Ws[i] = W[i];
    if (tid < CH) bs[tid] = bias[tid];
    __syncthreads();

    const int b = blockIdx.y;
    const int n = blockIdx.x * 128 + tid;

    float acc[CH];
    #pragma unroll
    for (int o = 0; o < CH; o++) acc[o] = bs[o];

    const float* ic = inp + (size_t)b * CH * NTOK + n;
    #pragma unroll
    for (int c4 = 0; c4 < CH / 4; c4++) {
        const float x0 = ic[(size_t)(c4 * 4 + 0) * NTOK];
        const float x1 = ic[(size_t)(c4 * 4 + 1) * NTOK];
        const float x2 = ic[(size_t)(c4 * 4 + 2) * NTOK];
        const float x3 = ic[(size_t)(c4 * 4 + 3) * NTOK];
        #pragma unroll
        for (int o = 0; o < CH; o++) {
            const float4 w = *(const float4*)&Ws[o * CH + c4 * 4];
            acc[o] += w.x * x0 + w.y * x1 + w.z * x2 + w.w * x3;
        }
    }

    if (z == 2) {
        __half* vd = g_V + (size_t)b * CH * NTOK + n;
        #pragma unroll
        for (int o = 0; o < CH; o++)
            vd[(size_t)o * NTOK] = __float2half_rn(acc[o]);   // coalesced
    } else {
        if (z == 0) {
            const float qs = SCALE * LOG2E;
            #pragma unroll
            for (int o = 0; o < CH; o++) acc[o] *= qs;
        }
        __half* dst = ((z == 0) ? g_Q : g_K) + ((size_t)(b * NTOK + n)) * CH;
        #pragma unroll
        for (int o8 = 0; o8 < 8; o8++) {
            __half2 h0 = __floats2half2_rn(acc[o8 * 8 + 0], acc[o8 * 8 + 1]);
            __half2 h1 = __floats2half2_rn(acc[o8 * 8 + 2], acc[o8 * 8 + 3]);
            __half2 h2 = __floats2half2_rn(acc[o8 * 8 + 4], acc[o8 * 8 + 5]);
            __half2 h3 = __floats2half2_rn(acc[o8 * 8 + 6], acc[o8 * 8 + 7]);
            uint4 u;
            u.x = *(uint32_t*)&h0; u.y = *(uint32_t*)&h1;
            u.z = *(uint32_t*)&h2; u.w = *(uint32_t*)&h3;
            ((uint4*)dst)[o8] = u;            // per-thread contiguous 128B row
        }
    }
}

// ---------------------------------------------------------------------------
// Split-KV FA2 fp16 attention. 256 threads = 8 warps.
// Warp w: rg = w&3 (rows rg*16..+15), ks = w>>2 (KV half).
// Each 128-thread group stages ITS OWN stream and syncs with a NAMED barrier
// (bar.sync ks+1) -> the two groups drift and stagger on each SMSP.
// K/V fragments via ldmatrix.x4 (conflict-free @144B row stride).
// smem: Qs[64][PH] @0; K [2 streams][3][64][PH] @9216; V @64512. 119808 B.
// ---------------------------------------------------------------------------
#define QS_B 0
#define KS_B 9216
#define VS_B (KS_B + 6 * 9216)
#define SMEM_BYTES (VS_B + 6 * 9216)   // 119808

__global__ __launch_bounds__(256, 1) void attn_kernel(float* __restrict__ out)
{
    extern __shared__ char smc[];
    const uint32_t sb = (uint32_t)__cvta_generic_to_shared(smc);

    const int b    = blockIdx.y;
    const int m0   = blockIdx.x * BM;
    const int tid  = threadIdx.x;
    const int lane = tid & 31;
    const int w    = tid >> 5;
    const int rg   = w & 3;
    const int ks   = w >> 2;
    const int gtid = tid & 127;          // thread-in-group
    const int gid  = lane >> 2;
    const int lc   = lane & 3;
    const int rlow  = rg * 16 + gid;
    const int rhigh = rlow + 8;

    // ldmatrix lane offset: matrix m = lane>>3, row r = lane&7
    // matrices per x4: {ntp*2, klo}, {ntp*2, khi}, {ntp*2+1, klo}, {ntp*2+1, khi}
    const int lmm = lane >> 3, lmr = lane & 7;
    const uint32_t lmoff =
        (uint32_t)((((lmm >> 1) * 8 + lmr) * 144) + (lmm & 1) * 16);

    // group-local staging of own stream only (8 cp16/thread)
    auto stage_kv = [&](int slot, int tl) {
        const int tn = ks * NTH + tl;
        const uint32_t koff = sb + KS_B + (ks * 3 + slot) * 9216;
        const uint32_t voff = sb + VS_B + (ks * 3 + slot) * 9216;
        #pragma unroll
        for (int i = 0; i < 4; i++) {
            const int j = gtid + i * 128;     // 0..511
            const int r = j >> 3, c8 = j & 7;
            cp16(koff + r * 144 + c8 * 16,
                 g_K + ((size_t)(b * NTOK + tn * BN) + r) * CH + c8 * 8);
            cp16(voff + r * 144 + c8 * 16,
                 g_V + (size_t)b * CH * NTOK + (size_t)r * NTOK
                     + tn * BN + c8 * 8);
        }
    };

    // ---- prologue ----
    {
        #pragma unroll
        for (int i = 0; i < 2; i++) {
            const int j = tid + i * 256;
            const int r = j >> 3, c8 = j & 7;
            cp16(sb + QS_B + r * 144 + c8 * 16,
                 g_Q + ((size_t)(b * NTOK + m0) + r) * CH + c8 * 8);
        }
        stage_kv(0, 0);
        asm volatile("cp.async.commit_group;");
        stage_kv(1, 1);
        asm volatile("cp.async.commit_group;");
        asm volatile("cp.async.wait_group 1;" ::: "memory");
        __syncthreads();                      // Q + slot0 visible to all
    }

    // ---- persistent Q A-fragments ----
    const __half* Qs = (const __half*)(smc + QS_B);
    uint32_t qa[4][4];
    #pragma unroll
    for (int kt = 0; kt < 4; kt++) {
        qa[kt][0] = *(const uint32_t*)&Qs[rlow  * PH + kt * 16 + 2 * lc];
        qa[kt][1] = *(const uint32_t*)&Qs[rhigh * PH + kt * 16 + 2 * lc];
        qa[kt][2] = *(const uint32_t*)&Qs[rlow  * PH + kt * 16 + 2 * lc + 8];
        qa[kt][3] = *(const uint32_t*)&Qs[rhigh * PH + kt * 16 + 2 * lc + 8];
    }

    float acc[8][4];
    #pragma unroll
    for (int nt = 0; nt < 8; nt++)
        #pragma unroll
        for (int i = 0; i < 4; i++) acc[nt][i] = 0.f;
    float mlo_run = -1e30f, mhi_run = -1e30f, llo = 0.f, lhi = 0.f;

    const int barid = ks + 1;

    for (int t = 0; t < NTH; t++) {
        if (t > 0) {
            asm volatile("cp.async.wait_group 1;" ::: "memory");
            asm volatile("bar.sync %0, 128;" :: "r"(barid) : "memory");
        }
        {   // prefetch own stream tile t+2
            int tl = t + 2; if (tl >= NTH) tl -= NTH;
            stage_kv((t + 2) % 3, tl);
            asm volatile("cp.async.commit_group;");
        }

        const uint32_t kbase = sb + KS_B + (ks * 3 + (t % 3)) * 9216 + lmoff;
        const uint32_t vbase = sb + VS_B + (ks * 3 + (t % 3)) * 9216 + lmoff;

        // ---- scores S[16][64]: 16 ldmatrix.x4 + 32 mma ----
        float s[8][4];
        #pragma unroll
        for (int nt = 0; nt < 8; nt++)
            #pragma unroll
            for (int i = 0; i < 4; i++) s[nt][i] = 0.f;

        #pragma unroll
        for (int kt = 0; kt < 4; kt++) {
            #pragma unroll
            for (int ntp = 0; ntp < 4; ntp++) {
                uint32_t r0, r1, r2, r3;
                ldm4(r0, r1, r2, r3, kbase + ntp * 2304 + kt * 32);
                mma_f16(s[2 * ntp],     qa[kt], r0, r1);
                mma_f16(s[2 * ntp + 1], qa[kt], r2, r3);
            }
        }

        // ---- warp-local softmax ----
        float tmlo = -1e30f, tmhi = -1e30f;
        #pragma unroll
        for (int nt = 0; nt < 8; nt++) {
            tmlo = fmaxf(tmlo, fmaxf(s[nt][0], s[nt][1]));
            tmhi = fmaxf(tmhi, fmaxf(s[nt][2], s[nt][3]));
        }
        tmlo = fmaxf(tmlo, __shfl_xor_sync(0xffffffffu, tmlo, 1));
        tmlo = fmaxf(tmlo, __shfl_xor_sync(0xffffffffu, tmlo, 2));
        tmhi = fmaxf(tmhi, __shfl_xor_sync(0xffffffffu, tmhi, 1));
        tmhi = fmaxf(tmhi, __shfl_xor_sync(0xffffffffu, tmhi, 2));
        const float mnlo = fmaxf(mlo_run, tmlo);
        const float mnhi = fmaxf(mhi_run, tmhi);
        const float alo  = exp2f(mlo_run - mnlo);
        const float ahi  = exp2f(mhi_run - mnhi);
        mlo_run = mnlo; mhi_run = mnhi;

        uint32_t pa[4][4];
        float slo = 0.f, shi = 0.f;
        #pragma unroll
        for (int nt = 0; nt < 8; nt++) {
            float p0 = exp2f(s[nt][0] - mnlo);
            float p1 = exp2f(s[nt][1] - mnlo);
            float p2 = exp2f(s[nt][2] - mnhi);
            float p3 = exp2f(s[nt][3] - mnhi);
            slo += p0 + p1;  shi += p2 + p3;
            __half2 lo2 = __floats2half2_rn(p0, p1);
            __half2 hi2 = __floats2half2_rn(p2, p3);
            pa[nt >> 1][(nt & 1) * 2]     = *(uint32_t*)&lo2;
            pa[nt >> 1][(nt & 1) * 2 + 1] = *(uint32_t*)&hi2;
        }
        slo += __shfl_xor_sync(0xffffffffu, slo, 1);
        slo += __shfl_xor_sync(0xffffffffu, slo, 2);
        shi += __shfl_xor_sync(0xffffffffu, shi, 1);
        shi += __shfl_xor_sync(0xffffffffu, shi, 2);
        llo = llo * alo + slo;
        lhi = lhi * ahi + shi;

        // ---- PV: 16 ldmatrix.x4 + 32 mma ----
        #pragma unroll
        for (int nt = 0; nt < 8; nt++) {
            acc[nt][0] *= alo; acc[nt][1] *= alo;
            acc[nt][2] *= ahi; acc[nt][3] *= ahi;
        }
        #pragma unroll
        for (int kt = 0; kt < 4; kt++) {
            #pragma unroll
            for (int ntp = 0; ntp < 4; ntp++) {
                uint32_t r0, r1, r2, r3;
                ldm4(r0, r1, r2, r3, vbase + ntp * 2304 + kt * 32);
                mma_f16(acc[2 * ntp],     pa[kt], r0, r1);
                mma_f16(acc[2 * ntp + 1], pa[kt], r2, r3);
            }
        }
    }

    // ---- merge the two KV halves (partner warps, pointwise per lane) ----
    asm volatile("cp.async.wait_group 0;" ::: "memory");
    __syncthreads();
    float* mg = (float*)smc;                  // reuse Q/K smem (all cp drained)
    const int mbase = (rg * 32 + lane) * 37;  // stride 37: conflict-free
    if (ks == 1) {
        #pragma unroll
        for (int nt = 0; nt < 8; nt++)
            #pragma unroll
            for (int i = 0; i < 4; i++) mg[mbase + nt * 4 + i] = acc[nt][i];
        mg[mbase + 32] = mlo_run;
        mg[mbase + 33] = mhi_run;
        mg[mbase + 34] = llo;
        mg[mbase + 35] = lhi;
    }
    __syncthreads();
    if (ks == 0) {
        const float m1lo = mg[mbase + 32], m1hi = mg[mbase + 33];
        const float l1lo = mg[mbase + 34], l1hi = mg[mbase + 35];
        const float Mlo = fmaxf(mlo_run, m1lo);
        const float Mhi = fmaxf(mhi_run, m1hi);
        const float c0lo = exp2f(mlo_run - Mlo), c1lo = exp2f(m1lo - Mlo);
        const float c0hi = exp2f(mhi_run - Mhi), c1hi = exp2f(m1hi - Mhi);
        const float Llo = llo * c0lo + l1lo * c1lo;
        const float Lhi = lhi * c0hi + l1hi * c1hi;
        const float ilo = c0lo / Llo, jlo = c1lo / Llo;
        const float ihi = c0hi / Lhi, jhi = c1hi / Lhi;

        float* ob = out + (size_t)b * CH * NTOK + m0;
        #pragma unroll
        for (int nt = 0; nt < 8; nt++) {
            const int c = nt * 8 + 2 * lc;
            const float o0 = acc[nt][0] * ilo + mg[mbase + nt * 4 + 0] * jlo;
            const float o1 = acc[nt][1] * ilo + mg[mbase + nt * 4 + 1] * jlo;
            const float o2 = acc[nt][2] * ihi + mg[mbase + nt * 4 + 2] * jhi;
            const float o3 = acc[nt][3] * ihi + mg[mbase + nt * 4 + 3] * jhi;
            ob[(size_t)c * NTOK + rlow]        = o0;
            ob[(size_t)(c + 1) * NTOK + rlow]  = o1;
            ob[(size_t)c * NTOK + rhigh]       = o2;
            ob[(size_t)(c + 1) * NTOK + rhigh] = o3;
        }
    }
}

// ---------------------------------------------------------------------------
extern "C" void kernel_launch(void* const* d_in, const int* in_sizes, int n_in,
                              void* d_out, int out_size)
{
    const float* x  = (const float*)d_in[0];
    const float* h  = (const float*)d_in[1];
    const float* Wq = (const float*)d_in[2];
    const float* bq = (const float*)d_in[3];
    const float* Wk = (const float*)d_in[4];
    const float* bk = (const float*)d_in[5];
    const float* Wv = (const float*)d_in[6];
    const float* bv = (const float*)d_in[7];
    float* out = (float*)d_out;

    cudaFuncSetAttribute(attn_kernel,
                         cudaFuncAttributeMaxDynamicSharedMemorySize, SMEM_BYTES);

    proj_kernel<<<dim3(NTOK / 128, BATCH, 3), 128>>>(x, h, Wq, bq, Wk, bk, Wv, bv);
    attn_kernel<<<dim3(NTOK / BM, BATCH), 256, SMEM_BYTES>>>(out);
}

// round 8
// speedup vs baseline: 1.4458x; 1.2743x over previous
#include <cuda_runtime.h>
#include <cuda_fp16.h>
#include <cstdint>

#define BATCH 2
#define CH    64
#define NTOK  4608
#define BM    64
#define BN    64
#define NT    72               // total KV tiles
#define NTH   36               // tiles per KV half
#define SCALE 0.125f
#define LOG2E 1.4426950408889634f
#define PH    72               // padded tile row length in halves (144 B)

// Scratch (fp16): Q,K token-major [B][N][C]; V channel-major [B][C][N]
__device__ __half g_Q[BATCH * NTOK * CH];
__device__ __half g_K[BATCH * NTOK * CH];
__device__ __half g_V[BATCH * CH * NTOK];

// ---------------------------------------------------------------------------
__device__ __forceinline__ void mma_f16(float* c, const uint32_t* a,
                                        uint32_t b0, uint32_t b1) {
    asm volatile(
        "mma.sync.aligned.m16n8k16.row.col.f32.f16.f16.f32 "
        "{%0,%1,%2,%3}, {%4,%5,%6,%7}, {%8,%9}, {%0,%1,%2,%3};"
        : "+f"(c[0]), "+f"(c[1]), "+f"(c[2]), "+f"(c[3])
        : "r"(a[0]), "r"(a[1]), "r"(a[2]), "r"(a[3]), "r"(b0), "r"(b1));
}
__device__ __forceinline__ void ldm4(uint32_t& r0, uint32_t& r1,
                                     uint32_t& r2, uint32_t& r3, uint32_t addr) {
    asm volatile("ldmatrix.sync.aligned.m8n8.x4.shared.b16 {%0,%1,%2,%3}, [%4];"
                 : "=r"(r0), "=r"(r1), "=r"(r2), "=r"(r3) : "r"(addr));
}
__device__ __forceinline__ void cp16(uint32_t dst, const void* src) {
    asm volatile("cp.async.ca.shared.global [%0], [%1], 16;"
                 :: "r"(dst), "l"(src));
}

// ---------------------------------------------------------------------------
// Tensor-core projection. Block = 128 tokens, 256 threads (8 warps).
// Warp w: tokens w*16..w*16+15, all 64 outputs. A = input tokens (fp16),
// B = W rows (fp16, ldmatrix.x4 @144B stride). fp32 accum, bias in epilogue.
// z=0: Q=(Wq x + bq)*SCALE*LOG2E -> [n][c];  z=1: K -> [n][c];
// z=2: V -> TRANSPOSED [c][n].
// ---------------------------------------------------------------------------
__global__ __launch_bounds__(256) void proj_kernel(
    const float* __restrict__ x, const float* __restrict__ h,
    const float* __restrict__ Wq, const float* __restrict__ bq,
    const float* __restrict__ Wk, const float* __restrict__ bk,
    const float* __restrict__ Wv, const float* __restrict__ bv)
{
    __shared__ __half Wh[64 * PH];     // W rows [o][c], 144B stride
    __shared__ __half Xh[128 * PH];    // tokens [n][c], 144B stride
    __shared__ float  bsh[64];

    const int z = blockIdx.z;
    const float* inp  = (z == 0) ? x  : h;
    const float* W    = (z == 0) ? Wq : (z == 1) ? Wk : Wv;
    const float* bias = (z == 0) ? bq : (z == 1) ? bk : bv;

    const int tid = threadIdx.x;
    const int b   = blockIdx.y;
    const int n0  = blockIdx.x * 128;

    // W -> fp16 smem
    #pragma unroll
    for (int i = tid; i < 64 * 64; i += 256) {
        const int o = i >> 6, c = i & 63;
        Wh[o * PH + c] = __float2half_rn(W[i]);
    }
    if (tid < 64) bsh[tid] = bias[tid];

    // input slice [64 c][128 n] -> fp16, transposed into Xh[n][c]
    const float* ib = inp + (size_t)b * CH * NTOK + n0;
    #pragma unroll
    for (int i = tid; i < 64 * 128; i += 256) {
        const int c = i >> 7, n = i & 127;
        Xh[n * PH + c] = __float2half_rn(ib[(size_t)c * NTOK + n]);
    }
    __syncthreads();

    const int lane = tid & 31;
    const int w    = tid >> 5;
    const int gid  = lane >> 2;
    const int lc   = lane & 3;
    const int rlow  = w * 16 + gid;    // block-local token row
    const int rhigh = rlow + 8;

    // A-fragments from Xh (same pattern as attn Q)
    uint32_t qa[4][4];
    #pragma unroll
    for (int kt = 0; kt < 4; kt++) {
        qa[kt][0] = *(const uint32_t*)&Xh[rlow  * PH + kt * 16 + 2 * lc];
        qa[kt][1] = *(const uint32_t*)&Xh[rhigh * PH + kt * 16 + 2 * lc];
        qa[kt][2] = *(const uint32_t*)&Xh[rlow  * PH + kt * 16 + 2 * lc + 8];
        qa[kt][3] = *(const uint32_t*)&Xh[rhigh * PH + kt * 16 + 2 * lc + 8];
    }

    // ldmatrix offsets into Wh (same formula as attn)
    const int lmm = lane >> 3, lmr = lane & 7;
    const uint32_t lmoff =
        (uint32_t)((((lmm >> 1) * 8 + lmr) * 144) + (lmm & 1) * 16);
    const uint32_t wbase =
        (uint32_t)__cvta_generic_to_shared(Wh) + lmoff;

    float acc[8][4];
    #pragma unroll
    for (int nt = 0; nt < 8; nt++)
        #pragma unroll
        for (int i = 0; i < 4; i++) acc[nt][i] = 0.f;

    #pragma unroll
    for (int kt = 0; kt < 4; kt++) {
        #pragma unroll
        for (int ntp = 0; ntp < 4; ntp++) {
            uint32_t r0, r1, r2, r3;
            ldm4(r0, r1, r2, r3, wbase + ntp * 2304 + kt * 32);
            mma_f16(acc[2 * ntp],     qa[kt], r0, r1);
            mma_f16(acc[2 * ntp + 1], qa[kt], r2, r3);
        }
    }

    // epilogue: bias (+ scale for Q), store
    if (z == 2) {
        __half* vd = g_V + (size_t)b * CH * NTOK;
        #pragma unroll
        for (int nt = 0; nt < 8; nt++) {
            const int c0 = nt * 8 + 2 * lc;
            const float b0 = bsh[c0], b1 = bsh[c0 + 1];
            vd[(size_t)c0 * NTOK + n0 + rlow]        = __float2half_rn(acc[nt][0] + b0);
            vd[(size_t)(c0 + 1) * NTOK + n0 + rlow]  = __float2half_rn(acc[nt][1] + b1);
            vd[(size_t)c0 * NTOK + n0 + rhigh]       = __float2half_rn(acc[nt][2] + b0);
            vd[(size_t)(c0 + 1) * NTOK + n0 + rhigh] = __float2half_rn(acc[nt][3] + b1);
        }
    } else {
        const float qs = (z == 0) ? SCALE * LOG2E : 1.f;
        __half* base = (z == 0) ? g_Q : g_K;
        __half* dlo = base + ((size_t)(b * NTOK + n0 + rlow))  * CH;
        __half* dhi = base + ((size_t)(b * NTOK + n0 + rhigh)) * CH;
        #pragma unroll
        for (int nt = 0; nt < 8; nt++) {
            const int c0 = nt * 8 + 2 * lc;
            const float b0 = bsh[c0], b1 = bsh[c0 + 1];
            __half2 lo = __floats2half2_rn((acc[nt][0] + b0) * qs,
                                           (acc[nt][1] + b1) * qs);
            __half2 hi = __floats2half2_rn((acc[nt][2] + b0) * qs,
                                           (acc[nt][3] + b1) * qs);
            *(__half2*)&dlo[c0] = lo;
            *(__half2*)&dhi[c0] = hi;
        }
    }
}

// ---------------------------------------------------------------------------
// Split-KV FA2 fp16 attention (unchanged from round 7).
// ---------------------------------------------------------------------------
#define QS_B 0
#define KS_B 9216
#define VS_B (KS_B + 6 * 9216)
#define SMEM_BYTES (VS_B + 6 * 9216)   // 119808

__global__ __launch_bounds__(256, 1) void attn_kernel(float* __restrict__ out)
{
    extern __shared__ char smc[];
    const uint32_t sb = (uint32_t)__cvta_generic_to_shared(smc);

    const int b    = blockIdx.y;
    const int m0   = blockIdx.x * BM;
    const int tid  = threadIdx.x;
    const int lane = tid & 31;
    const int w    = tid >> 5;
    const int rg   = w & 3;
    const int ks   = w >> 2;
    const int gtid = tid & 127;
    const int gid  = lane >> 2;
    const int lc   = lane & 3;
    const int rlow  = rg * 16 + gid;
    const int rhigh = rlow + 8;

    const int lmm = lane >> 3, lmr = lane & 7;
    const uint32_t lmoff =
        (uint32_t)((((lmm >> 1) * 8 + lmr) * 144) + (lmm & 1) * 16);

    auto stage_kv = [&](int slot, int tl) {
        const int tn = ks * NTH + tl;
        const uint32_t koff = sb + KS_B + (ks * 3 + slot) * 9216;
        const uint32_t voff = sb + VS_B + (ks * 3 + slot) * 9216;
        #pragma unroll
        for (int i = 0; i < 4; i++) {
            const int j = gtid + i * 128;
            const int r = j >> 3, c8 = j & 7;
            cp16(koff + r * 144 + c8 * 16,
                 g_K + ((size_t)(b * NTOK + tn * BN) + r) * CH + c8 * 8);
            cp16(voff + r * 144 + c8 * 16,
                 g_V + (size_t)b * CH * NTOK + (size_t)r * NTOK
                     + tn * BN + c8 * 8);
        }
    };

    {
        #pragma unroll
        for (int i = 0; i < 2; i++) {
            const int j = tid + i * 256;
            const int r = j >> 3, c8 = j & 7;
            cp16(sb + QS_B + r * 144 + c8 * 16,
                 g_Q + ((size_t)(b * NTOK + m0) + r) * CH + c8 * 8);
        }
        stage_kv(0, 0);
        asm volatile("cp.async.commit_group;");
        stage_kv(1, 1);
        asm volatile("cp.async.commit_group;");
        asm volatile("cp.async.wait_group 1;" ::: "memory");
        __syncthreads();
    }

    const __half* Qs = (const __half*)(smc + QS_B);
    uint32_t qa[4][4];
    #pragma unroll
    for (int kt = 0; kt < 4; kt++) {
        qa[kt][0] = *(const uint32_t*)&Qs[rlow  * PH + kt * 16 + 2 * lc];
        qa[kt][1] = *(const uint32_t*)&Qs[rhigh * PH + kt * 16 + 2 * lc];
        qa[kt][2] = *(const uint32_t*)&Qs[rlow  * PH + kt * 16 + 2 * lc + 8];
        qa[kt][3] = *(const uint32_t*)&Qs[rhigh * PH + kt * 16 + 2 * lc + 8];
    }

    float acc[8][4];
    #pragma unroll
    for (int nt = 0; nt < 8; nt++)
        #pragma unroll
        for (int i = 0; i < 4; i++) acc[nt][i] = 0.f;
    float mlo_run = -1e30f, mhi_run = -1e30f, llo = 0.f, lhi = 0.f;

    const int barid = ks + 1;

    for (int t = 0; t < NTH; t++) {
        if (t > 0) {
            asm volatile("cp.async.wait_group 1;" ::: "memory");
            asm volatile("bar.sync %0, 128;" :: "r"(barid) : "memory");
        }
        {
            int tl = t + 2; if (tl >= NTH) tl -= NTH;
            stage_kv((t + 2) % 3, tl);
            asm volatile("cp.async.commit_group;");
        }

        const uint32_t kbase = sb + KS_B + (ks * 3 + (t % 3)) * 9216 + lmoff;
        const uint32_t vbase = sb + VS_B + (ks * 3 + (t % 3)) * 9216 + lmoff;

        float s[8][4];
        #pragma unroll
        for (int nt = 0; nt < 8; nt++)
            #pragma unroll
            for (int i = 0; i < 4; i++) s[nt][i] = 0.f;

        #pragma unroll
        for (int kt = 0; kt < 4; kt++) {
            #pragma unroll
            for (int ntp = 0; ntp < 4; ntp++) {
                uint32_t r0, r1, r2, r3;
                ldm4(r0, r1, r2, r3, kbase + ntp * 2304 + kt * 32);
                mma_f16(s[2 * ntp],     qa[kt], r0, r1);
                mma_f16(s[2 * ntp + 1], qa[kt], r2, r3);
            }
        }

        float tmlo = -1e30f, tmhi = -1e30f;
        #pragma unroll
        for (int nt = 0; nt < 8; nt++) {
            tmlo = fmaxf(tmlo, fmaxf(s[nt][0], s[nt][1]));
            tmhi = fmaxf(tmhi, fmaxf(s[nt][2], s[nt][3]));
        }
        tmlo = fmaxf(tmlo, __shfl_xor_sync(0xffffffffu, tmlo, 1));
        tmlo = fmaxf(tmlo, __shfl_xor_sync(0xffffffffu, tmlo, 2));
        tmhi = fmaxf(tmhi, __shfl_xor_sync(0xffffffffu, tmhi, 1));
        tmhi = fmaxf(tmhi, __shfl_xor_sync(0xffffffffu, tmhi, 2));
        const float mnlo = fmaxf(mlo_run, tmlo);
        const float mnhi = fmaxf(mhi_run, tmhi);
        const float alo  = exp2f(mlo_run - mnlo);
        const float ahi  = exp2f(mhi_run - mnhi);
        mlo_run = mnlo; mhi_run = mnhi;

        uint32_t pa[4][4];
        float slo = 0.f, shi = 0.f;
        #pragma unroll
        for (int nt = 0; nt < 8; nt++) {
            float p0 = exp2f(s[nt][0] - mnlo);
            float p1 = exp2f(s[nt][1] - mnlo);
            float p2 = exp2f(s[nt][2] - mnhi);
            float p3 = exp2f(s[nt][3] - mnhi);
            slo += p0 + p1;  shi += p2 + p3;
            __half2 lo2 = __floats2half2_rn(p0, p1);
            __half2 hi2 = __floats2half2_rn(p2, p3);
            pa[nt >> 1][(nt & 1) * 2]     = *(uint32_t*)&lo2;
            pa[nt >> 1][(nt & 1) * 2 + 1] = *(uint32_t*)&hi2;
        }
        slo += __shfl_xor_sync(0xffffffffu, slo, 1);
        slo += __shfl_xor_sync(0xffffffffu, slo, 2);
        shi += __shfl_xor_sync(0xffffffffu, shi, 1);
        shi += __shfl_xor_sync(0xffffffffu, shi, 2);
        llo = llo * alo + slo;
        lhi = lhi * ahi + shi;

        #pragma unroll
        for (int nt = 0; nt < 8; nt++) {
            acc[nt][0] *= alo; acc[nt][1] *= alo;
            acc[nt][2] *= ahi; acc[nt][3] *= ahi;
        }
        #pragma unroll
        for (int kt = 0; kt < 4; kt++) {
            #pragma unroll
            for (int ntp = 0; ntp < 4; ntp++) {
                uint32_t r0, r1, r2, r3;
                ldm4(r0, r1, r2, r3, vbase + ntp * 2304 + kt * 32);
                mma_f16(acc[2 * ntp],     pa[kt], r0, r1);
                mma_f16(acc[2 * ntp + 1], pa[kt], r2, r3);
            }
        }
    }

    asm volatile("cp.async.wait_group 0;" ::: "memory");
    __syncthreads();
    float* mg = (float*)smc;
    const int mbase = (rg * 32 + lane) * 37;
    if (ks == 1) {
        #pragma unroll
        for (int nt = 0; nt < 8; nt++)
            #pragma unroll
            for (int i = 0; i < 4; i++) mg[mbase + nt * 4 + i] = acc[nt][i];
        mg[mbase + 32] = mlo_run;
        mg[mbase + 33] = mhi_run;
        mg[mbase + 34] = llo;
        mg[mbase + 35] = lhi;
    }
    __syncthreads();
    if (ks == 0) {
        const float m1lo = mg[mbase + 32], m1hi = mg[mbase + 33];
        const float l1lo = mg[mbase + 34], l1hi = mg[mbase + 35];
        const float Mlo = fmaxf(mlo_run, m1lo);
        const float Mhi = fmaxf(mhi_run, m1hi);
        const float c0lo = exp2f(mlo_run - Mlo), c1lo = exp2f(m1lo - Mlo);
        const float c0hi = exp2f(mhi_run - Mhi), c1hi = exp2f(m1hi - Mhi);
        const float Llo = llo * c0lo + l1lo * c1lo;
        const float Lhi = lhi * c0hi + l1hi * c1hi;
        const float ilo = c0lo / Llo, jlo = c1lo / Llo;
        const float ihi = c0hi / Lhi, jhi = c1hi / Lhi;

        float* ob = out + (size_t)b * CH * NTOK + m0;
        #pragma unroll
        for (int nt = 0; nt < 8; nt++) {
            const int c = nt * 8 + 2 * lc;
            const float o0 = acc[nt][0] * ilo + mg[mbase + nt * 4 + 0] * jlo;
            const float o1 = acc[nt][1] * ilo + mg[mbase + nt * 4 + 1] * jlo;
            const float o2 = acc[nt][2] * ihi + mg[mbase + nt * 4 + 2] * jhi;
            const float o3 = acc[nt][3] * ihi + mg[mbase + nt * 4 + 3] * jhi;
            ob[(size_t)c * NTOK + rlow]        = o0;
            ob[(size_t)(c + 1) * NTOK + rlow]  = o1;
            ob[(size_t)c * NTOK + rhigh]       = o2;
            ob[(size_t)(c + 1) * NTOK + rhigh] = o3;
        }
    }
}

// ---------------------------------------------------------------------------
extern "C" void kernel_launch(void* const* d_in, const int* in_sizes, int n_in,
                              void* d_out, int out_size)
{
    const float* x  = (const float*)d_in[0];
    const float* h  = (const float*)d_in[1];
    const float* Wq = (const float*)d_in[2];
    const float* bq = (const float*)d_in[3];
    const float* Wk = (const float*)d_in[4];
    const float* bk = (const float*)d_in[5];
    const float* Wv = (const float*)d_in[6];
    const float* bv = (const float*)d_in[7];
    float* out = (float*)d_out;

    cudaFuncSetAttribute(attn_kernel,
                         cudaFuncAttributeMaxDynamicSharedMemorySize, SMEM_BYTES);

    proj_kernel<<<dim3(NTOK / 128, BATCH, 3), 256>>>(x, h, Wq, bq, Wk, bk, Wv, bv);
    attn_kernel<<<dim3(NTOK / BM, BATCH), 256, SMEM_BYTES>>>(out);
}

// round 9
// speedup vs baseline: 1.5874x; 1.0979x over previous
#include <cuda_runtime.h>
#include <cuda_fp16.h>
#include <cstdint>

#define BATCH 2
#define CH    64
#define NTOK  4608
#define BM    64
#define BN    64
#define NT    72               // total KV tiles
#define NS    3                // KV streams
#define NTH   24               // tiles per stream
#define SCALE 0.125f
#define LOG2E 1.4426950408889634f
#define PH    72               // padded tile row length in halves (144 B)

// Scratch (fp16): Q,K token-major [B][N][C]; V channel-major [B][C][N]
__device__ __half g_Q[BATCH * NTOK * CH];
__device__ __half g_K[BATCH * NTOK * CH];
__device__ __half g_V[BATCH * CH * NTOK];

// ---------------------------------------------------------------------------
__device__ __forceinline__ void mma_f16(float* c, const uint32_t* a,
                                        uint32_t b0, uint32_t b1) {
    asm volatile(
        "mma.sync.aligned.m16n8k16.row.col.f32.f16.f16.f32 "
        "{%0,%1,%2,%3}, {%4,%5,%6,%7}, {%8,%9}, {%0,%1,%2,%3};"
        : "+f"(c[0]), "+f"(c[1]), "+f"(c[2]), "+f"(c[3])
        : "r"(a[0]), "r"(a[1]), "r"(a[2]), "r"(a[3]), "r"(b0), "r"(b1));
}
__device__ __forceinline__ void ldm4(uint32_t& r0, uint32_t& r1,
                                     uint32_t& r2, uint32_t& r3, uint32_t addr) {
    asm volatile("ldmatrix.sync.aligned.m8n8.x4.shared.b16 {%0,%1,%2,%3}, [%4];"
                 : "=r"(r0), "=r"(r1), "=r"(r2), "=r"(r3) : "r"(addr));
}
__device__ __forceinline__ void cp16(uint32_t dst, const void* src) {
    asm volatile("cp.async.ca.shared.global [%0], [%1], 16;"
                 :: "r"(dst), "l"(src));
}

// ---------------------------------------------------------------------------
// Tensor-core projection (round-8) + coalesced V store via smem transpose.
// ---------------------------------------------------------------------------
__global__ __launch_bounds__(256) void proj_kernel(
    const float* __restrict__ x, const float* __restrict__ h,
    const float* __restrict__ Wq, const float* __restrict__ bq,
    const float* __restrict__ Wk, const float* __restrict__ bk,
    const float* __restrict__ Wv, const float* __restrict__ bv)
{
    __shared__ __half Wh[64 * PH];     // W rows [o][c], 144B stride
    __shared__ __half Xh[128 * PH];    // tokens [n][c]; later reused as V^T
    __shared__ float  bsh[64];

    const int z = blockIdx.z;
    const float* inp  = (z == 0) ? x  : h;
    const float* W    = (z == 0) ? Wq : (z == 1) ? Wk : Wv;
    const float* bias = (z == 0) ? bq : (z == 1) ? bk : bv;

    const int tid = threadIdx.x;
    const int b   = blockIdx.y;
    const int n0  = blockIdx.x * 128;

    #pragma unroll
    for (int i = tid; i < 64 * 64; i += 256) {
        const int o = i >> 6, c = i & 63;
        Wh[o * PH + c] = __float2half_rn(W[i]);
    }
    if (tid < 64) bsh[tid] = bias[tid];

    const float* ib = inp + (size_t)b * CH * NTOK + n0;
    #pragma unroll
    for (int i = tid; i < 64 * 128; i += 256) {
        const int c = i >> 7, n = i & 127;
        Xh[n * PH + c] = __float2half_rn(ib[(size_t)c * NTOK + n]);
    }
    __syncthreads();

    const int lane = tid & 31;
    const int w    = tid >> 5;
    const int gid  = lane >> 2;
    const int lc   = lane & 3;
    const int rlow  = w * 16 + gid;
    const int rhigh = rlow + 8;

    uint32_t qa[4][4];
    #pragma unroll
    for (int kt = 0; kt < 4; kt++) {
        qa[kt][0] = *(const uint32_t*)&Xh[rlow  * PH + kt * 16 + 2 * lc];
        qa[kt][1] = *(const uint32_t*)&Xh[rhigh * PH + kt * 16 + 2 * lc];
        qa[kt][2] = *(const uint32_t*)&Xh[rlow  * PH + kt * 16 + 2 * lc + 8];
        qa[kt][3] = *(const uint32_t*)&Xh[rhigh * PH + kt * 16 + 2 * lc + 8];
    }

    const int lmm = lane >> 3, lmr = lane & 7;
    const uint32_t lmoff =
        (uint32_t)((((lmm >> 1) * 8 + lmr) * 144) + (lmm & 1) * 16);
    const uint32_t wbase = (uint32_t)__cvta_generic_to_shared(Wh) + lmoff;

    float acc[8][4];
    #pragma unroll
    for (int nt = 0; nt < 8; nt++)
        #pragma unroll
        for (int i = 0; i < 4; i++) acc[nt][i] = 0.f;

    #pragma unroll
    for (int kt = 0; kt < 4; kt++) {
        #pragma unroll
        for (int ntp = 0; ntp < 4; ntp++) {
            uint32_t r0, r1, r2, r3;
            ldm4(r0, r1, r2, r3, wbase + ntp * 2304 + kt * 32);
            mma_f16(acc[2 * ntp],     qa[kt], r0, r1);
            mma_f16(acc[2 * ntp + 1], qa[kt], r2, r3);
        }
    }

    if (z == 2) {
        // V: transpose through smem, then coalesced half2 stores
        __syncthreads();                       // done reading Xh
        __half* Vt2 = Xh;                      // [64 c][132 n-pad]
        #pragma unroll
        for (int nt = 0; nt < 8; nt++) {
            const int c0 = nt * 8 + 2 * lc;
            Vt2[(c0)     * 132 + rlow]  = __float2half_rn(acc[nt][0] + bsh[c0]);
            Vt2[(c0 + 1) * 132 + rlow]  = __float2half_rn(acc[nt][1] + bsh[c0 + 1]);
            Vt2[(c0)     * 132 + rhigh] = __float2half_rn(acc[nt][2] + bsh[c0]);
            Vt2[(c0 + 1) * 132 + rhigh] = __float2half_rn(acc[nt][3] + bsh[c0 + 1]);
        }
        __syncthreads();
        __half* vd = g_V + (size_t)b * CH * NTOK + n0;
        #pragma unroll
        for (int i = tid; i < 64 * 64; i += 256) {
            const int c = i >> 6, n2 = (i & 63) * 2;
            *(__half2*)&vd[(size_t)c * NTOK + n2] = *(__half2*)&Vt2[c * 132 + n2];
        }
    } else {
        const float qs = (z == 0) ? SCALE * LOG2E : 1.f;
        __half* base = (z == 0) ? g_Q : g_K;
        __half* dlo = base + ((size_t)(b * NTOK + n0 + rlow))  * CH;
        __half* dhi = base + ((size_t)(b * NTOK + n0 + rhigh)) * CH;
        #pragma unroll
        for (int nt = 0; nt < 8; nt++) {
            const int c0 = nt * 8 + 2 * lc;
            const float b0 = bsh[c0], b1 = bsh[c0 + 1];
            __half2 lo = __floats2half2_rn((acc[nt][0] + b0) * qs,
                                           (acc[nt][1] + b1) * qs);
            __half2 hi = __floats2half2_rn((acc[nt][2] + b0) * qs,
                                           (acc[nt][3] + b1) * qs);
            *(__half2*)&dlo[c0] = lo;
            *(__half2*)&dhi[c0] = hi;
        }
    }
}

// ---------------------------------------------------------------------------
// 3-way split-KV FA2 fp16 attention. 384 threads = 12 warps.
// Warp w: rg = w&3 (rows rg*16..+15), ks = w>>2 in {0,1,2} (KV stream).
// Each 128-thread group stages its own triple-buffered stream, syncs with
// bar.sync ks+1 -> 3 independent groups interleave on every SMSP.
// smem: Qs @0; K [3 streams][3 slots] @9216; V @+9*9216. 175104 B.
// ---------------------------------------------------------------------------
#define QS_B 0
#define KS_B 9216
#define VS_B (KS_B + 9 * 9216)
#define SMEM_BYTES (VS_B + 9 * 9216)   // 175104

__global__ __launch_bounds__(384, 1) void attn_kernel(float* __restrict__ out)
{
    extern __shared__ char smc[];
    const uint32_t sb = (uint32_t)__cvta_generic_to_shared(smc);

    const int b    = blockIdx.y;
    const int m0   = blockIdx.x * BM;
    const int tid  = threadIdx.x;
    const int lane = tid & 31;
    const int w    = tid >> 5;
    const int rg   = w & 3;
    const int ks   = w >> 2;             // 0..2
    const int gtid = tid & 127;
    const int gid  = lane >> 2;
    const int lc   = lane & 3;
    const int rlow  = rg * 16 + gid;
    const int rhigh = rlow + 8;

    const int lmm = lane >> 3, lmr = lane & 7;
    const uint32_t lmoff =
        (uint32_t)((((lmm >> 1) * 8 + lmr) * 144) + (lmm & 1) * 16);

    auto stage_kv = [&](int slot, int tl) {
        const int tn = ks * NTH + tl;
        const uint32_t koff = sb + KS_B + (ks * 3 + slot) * 9216;
        const uint32_t voff = sb + VS_B + (ks * 3 + slot) * 9216;
        #pragma unroll
        for (int i = 0; i < 4; i++) {
            const int j = gtid + i * 128;
            const int r = j >> 3, c8 = j & 7;
            cp16(koff + r * 144 + c8 * 16,
                 g_K + ((size_t)(b * NTOK + tn * BN) + r) * CH + c8 * 8);
            cp16(voff + r * 144 + c8 * 16,
                 g_V + (size_t)b * CH * NTOK + (size_t)r * NTOK
                     + tn * BN + c8 * 8);
        }
    };

    {
        #pragma unroll
        for (int i = 0; i < 2; i++) {
            const int j = tid + i * 384;
            if (j < 512) {
                const int r = j >> 3, c8 = j & 7;
                cp16(sb + QS_B + r * 144 + c8 * 16,
                     g_Q + ((size_t)(b * NTOK + m0) + r) * CH + c8 * 8);
            }
        }
        stage_kv(0, 0);
        asm volatile("cp.async.commit_group;");
        stage_kv(1, 1);
        asm volatile("cp.async.commit_group;");
        asm volatile("cp.async.wait_group 1;" ::: "memory");
        __syncthreads();
    }

    const __half* Qs = (const __half*)(smc + QS_B);
    uint32_t qa[4][4];
    #pragma unroll
    for (int kt = 0; kt < 4; kt++) {
        qa[kt][0] = *(const uint32_t*)&Qs[rlow  * PH + kt * 16 + 2 * lc];
        qa[kt][1] = *(const uint32_t*)&Qs[rhigh * PH + kt * 16 + 2 * lc];
        qa[kt][2] = *(const uint32_t*)&Qs[rlow  * PH + kt * 16 + 2 * lc + 8];
        qa[kt][3] = *(const uint32_t*)&Qs[rhigh * PH + kt * 16 + 2 * lc + 8];
    }

    float acc[8][4];
    #pragma unroll
    for (int nt = 0; nt < 8; nt++)
        #pragma unroll
        for (int i = 0; i < 4; i++) acc[nt][i] = 0.f;
    float mlo_run = -1e30f, mhi_run = -1e30f, llo = 0.f, lhi = 0.f;

    const int barid = ks + 1;

    for (int t = 0; t < NTH; t++) {
        if (t > 0) {
            asm volatile("cp.async.wait_group 1;" ::: "memory");
            asm volatile("bar.sync %0, 128;" :: "r"(barid) : "memory");
        }
        {
            int tl = t + 2; if (tl >= NTH) tl -= NTH;
            stage_kv((t + 2) % 3, tl);
            asm volatile("cp.async.commit_group;");
        }

        const uint32_t kbase = sb + KS_B + (ks * 3 + (t % 3)) * 9216 + lmoff;
        const uint32_t vbase = sb + VS_B + (ks * 3 + (t % 3)) * 9216 + lmoff;

        float s[8][4];
        #pragma unroll
        for (int nt = 0; nt < 8; nt++)
            #pragma unroll
            for (int i = 0; i < 4; i++) s[nt][i] = 0.f;

        #pragma unroll
        for (int kt = 0; kt < 4; kt++) {
            #pragma unroll
            for (int ntp = 0; ntp < 4; ntp++) {
                uint32_t r0, r1, r2, r3;
                ldm4(r0, r1, r2, r3, kbase + ntp * 2304 + kt * 32);
                mma_f16(s[2 * ntp],     qa[kt], r0, r1);
                mma_f16(s[2 * ntp + 1], qa[kt], r2, r3);
            }
        }

        float tmlo = -1e30f, tmhi = -1e30f;
        #pragma unroll
        for (int nt = 0; nt < 8; nt++) {
            tmlo = fmaxf(tmlo, fmaxf(s[nt][0], s[nt][1]));
            tmhi = fmaxf(tmhi, fmaxf(s[nt][2], s[nt][3]));
        }
        tmlo = fmaxf(tmlo, __shfl_xor_sync(0xffffffffu, tmlo, 1));
        tmlo = fmaxf(tmlo, __shfl_xor_sync(0xffffffffu, tmlo, 2));
        tmhi = fmaxf(tmhi, __shfl_xor_sync(0xffffffffu, tmhi, 1));
        tmhi = fmaxf(tmhi, __shfl_xor_sync(0xffffffffu, tmhi, 2));
        const float mnlo = fmaxf(mlo_run, tmlo);
        const float mnhi = fmaxf(mhi_run, tmhi);
        const float alo  = exp2f(mlo_run - mnlo);
        const float ahi  = exp2f(mhi_run - mnhi);
        mlo_run = mnlo; mhi_run = mnhi;

        uint32_t pa[4][4];
        float slo = 0.f, shi = 0.f;
        #pragma unroll
        for (int nt = 0; nt < 8; nt++) {
            float p0 = exp2f(s[nt][0] - mnlo);
            float p1 = exp2f(s[nt][1] - mnlo);
            float p2 = exp2f(s[nt][2] - mnhi);
            float p3 = exp2f(s[nt][3] - mnhi);
            slo += p0 + p1;  shi += p2 + p3;
            __half2 lo2 = __floats2half2_rn(p0, p1);
            __half2 hi2 = __floats2half2_rn(p2, p3);
            pa[nt >> 1][(nt & 1) * 2]     = *(uint32_t*)&lo2;
            pa[nt >> 1][(nt & 1) * 2 + 1] = *(uint32_t*)&hi2;
        }
        slo += __shfl_xor_sync(0xffffffffu, slo, 1);
        slo += __shfl_xor_sync(0xffffffffu, slo, 2);
        shi += __shfl_xor_sync(0xffffffffu, shi, 1);
        shi += __shfl_xor_sync(0xffffffffu, shi, 2);
        llo = llo * alo + slo;
        lhi = lhi * ahi + shi;

        #pragma unroll
        for (int nt = 0; nt < 8; nt++) {
            acc[nt][0] *= alo; acc[nt][1] *= alo;
            acc[nt][2] *= ahi; acc[nt][3] *= ahi;
        }
        #pragma unroll
        for (int kt = 0; kt < 4; kt++) {
            #pragma unroll
            for (int ntp = 0; ntp < 4; ntp++) {
                uint32_t r0, r1, r2, r3;
                ldm4(r0, r1, r2, r3, vbase + ntp * 2304 + kt * 32);
                mma_f16(acc[2 * ntp],     pa[kt], r0, r1);
                mma_f16(acc[2 * ntp + 1], pa[kt], r2, r3);
            }
        }
    }

    // ---- 3-way merge across ks groups ----
    asm volatile("cp.async.wait_group 0;" ::: "memory");
    __syncthreads();
    float* mg = (float*)smc;                   // reuse staging smem
    if (ks != 0) {
        const int mbase = ((ks - 1) * 128 + rg * 32 + lane) * 37;
        #pragma unroll
        for (int nt = 0; nt < 8; nt++)
            #pragma unroll
            for (int i = 0; i < 4; i++) mg[mbase + nt * 4 + i] = acc[nt][i];
        mg[mbase + 32] = mlo_run;
        mg[mbase + 33] = mhi_run;
        mg[mbase + 34] = llo;
        mg[mbase + 35] = lhi;
    }
    __syncthreads();
    if (ks == 0) {
        const int m1 = (rg * 32 + lane) * 37;
        const int m2 = (128 + rg * 32 + lane) * 37;
        const float m1lo = mg[m1 + 32], m1hi = mg[m1 + 33];
        const float l1lo = mg[m1 + 34], l1hi = mg[m1 + 35];
        const float m2lo = mg[m2 + 32], m2hi = mg[m2 + 33];
        const float l2lo = mg[m2 + 34], l2hi = mg[m2 + 35];

        const float Mlo = fmaxf(mlo_run, fmaxf(m1lo, m2lo));
        const float Mhi = fmaxf(mhi_run, fmaxf(m1hi, m2hi));
        const float c0lo = exp2f(mlo_run - Mlo);
        const float c1lo = exp2f(m1lo - Mlo);
        const float c2lo = exp2f(m2lo - Mlo);
        const float c0hi = exp2f(mhi_run - Mhi);
        const float c1hi = exp2f(m1hi - Mhi);
        const float c2hi = exp2f(m2hi - Mhi);
        const float Llo = llo * c0lo + l1lo * c1lo + l2lo * c2lo;
        const float Lhi = lhi * c0hi + l1hi * c1hi + l2hi * c2hi;
        const float w0lo = c0lo / Llo, w1lo = c1lo / Llo, w2lo = c2lo / Llo;
        const float w0hi = c0hi / Lhi, w1hi = c1hi / Lhi, w2hi = c2hi / Lhi;

        float* ob = out + (size_t)b * CH * NTOK + m0;
        #pragma unroll
        for (int nt = 0; nt < 8; nt++) {
            const int c = nt * 8 + 2 * lc;
            const float o0 = acc[nt][0] * w0lo + mg[m1 + nt * 4 + 0] * w1lo
                           + mg[m2 + nt * 4 + 0] * w2lo;
            const float o1 = acc[nt][1] * w0lo + mg[m1 + nt * 4 + 1] * w1lo
                           + mg[m2 + nt * 4 + 1] * w2lo;
            const float o2 = acc[nt][2] * w0hi + mg[m1 + nt * 4 + 2] * w1hi
                           + mg[m2 + nt * 4 + 2] * w2hi;
            const float o3 = acc[nt][3] * w0hi + mg[m1 + nt * 4 + 3] * w1hi
                           + mg[m2 + nt * 4 + 3] * w2hi;
            ob[(size_t)c * NTOK + rlow]        = o0;
            ob[(size_t)(c + 1) * NTOK + rlow]  = o1;
            ob[(size_t)c * NTOK + rhigh]       = o2;
            ob[(size_t)(c + 1) * NTOK + rhigh] = o3;
        }
    }
}

// ---------------------------------------------------------------------------
extern "C" void kernel_launch(void* const* d_in, const int* in_sizes, int n_in,
                              void* d_out, int out_size)
{
    const float* x  = (const float*)d_in[0];
    const float* h  = (const float*)d_in[1];
    const float* Wq = (const float*)d_in[2];
    const float* bq = (const float*)d_in[3];
    const float* Wk = (const float*)d_in[4];
    const float* bk = (const float*)d_in[5];
    const float* Wv = (const float*)d_in[6];
    const float* bv = (const float*)d_in[7];
    float* out = (float*)d_out;

    cudaFuncSetAttribute(attn_kernel,
                         cudaFuncAttributeMaxDynamicSharedMemorySize, SMEM_BYTES);

    proj_kernel<<<dim3(NTOK / 128, BATCH, 3), 256>>>(x, h, Wq, bq, Wk, bk, Wv, bv);
    attn_kernel<<<dim3(NTOK / BM, BATCH), 384, SMEM_BYTES>>>(out);
}